// round 13
// baseline (speedup 1.0000x reference)
#include <cuda_runtime.h>
#include <cstdint>

// Problem sizes
#define S    4096
#define II   64
#define H    1024
#define NCTA 128
#define UPC  8        // hidden units per CTA (1 per warp, 8 warps)
#define CSTRIDE 64    // 64 uints = 256B between counter words (distinct LTS slices)

// ---------------------------------------------------------------------------
// Device-global scratch (allocation-free rule: __device__ arrays only)
//
// g_h:    double-buffered hidden state (plain f32; h_t lives in slot t&1).
// g_cnt8: EIGHT monotonic counters, one per warp-index w, each padded to its
//         own 256B-spaced line (bit 7 of the addr hash is transparent, so
//         256B stride -> different L2 slices; 128 same-address REDs per word
//         per step = the proven-benign R4/R8 level, NOT R9's 1024-on-one).
//
// Signaling: warp w's lane 0 publishes h[u] (__stcg) then immediately
// red.release.gpu.add(g_cnt8[w*CSTRIDE], 1)  — fires the moment the warp is
// done. Consumer: tid0 acquire-polls all 8 words >= 128*t, bar fans out.
// Cumulativity: all CTA threads' sweep reads precede bar B, which precedes
// each lane0's release-red, so the red covers the whole CTA's reads (WAR
// closed without any trailing bar). Discovery law respected: 1 poller/CTA.
// ---------------------------------------------------------------------------
__device__ float    g_h[2][H];
__device__ unsigned g_cnt8[UPC * CSTRIDE];

// ---------------------------------------------------------------------------
// Helpers
// ---------------------------------------------------------------------------
__device__ __forceinline__ unsigned long long pk2(float x, float y) {
    unsigned long long r;
    asm("mov.b64 %0, {%1,%2};" : "=l"(r) : "f"(x), "f"(y));
    return r;
}
__device__ __forceinline__ void upk2(unsigned long long a, float& x, float& y) {
    asm("mov.b64 {%0,%1}, %2;" : "=f"(x), "=f"(y) : "l"(a));
}
#define FMA2(acc, a, b) \
    asm("fma.rn.f32x2 %0, %1, %2, %0;" : "+l"(acc) : "l"(a), "l"(b))

__device__ __forceinline__ float sigf(float x) {
    return 1.0f / (1.0f + __expf(-x));
}
__device__ __forceinline__ float tanhfast(float x) {
    float ax = fabsf(x);
    float e  = __expf(-2.0f * ax);          // in (0,1], overflow-free
    float t  = __fdividef(1.0f - e, 1.0f + e);
    return copysignf(t, x);
}

// ---------------------------------------------------------------------------
// Kernel 0: reset state between graph replays (determinism requirement)
// ---------------------------------------------------------------------------
__global__ void reset_kernel() {
    int i = threadIdx.x;
    if (i < H) { g_h[0][i] = 0.0f; g_h[1][i] = 0.0f; }
    if (i < UPC * CSTRIDE) g_cnt8[i] = 0u;
}

// ---------------------------------------------------------------------------
// Kernel 1: persistent fused LSTM recurrence (input GEMM folded in).
// 128 CTAs x 256 threads, 1 CTA/SM. Warp w of CTA b owns hidden unit
// u = b*8 + w (gate rows u, H+u, 2H+u, 3H+u). Lane l holds W_hh column
// pairs (2l+64k) k=0..15 (64 packed f32x2) + W_ih column pair 2l in regs.
//
// Per-step protocol (TWO __syncthreads):
//   1. prefetch x_{t+1} (tid<16, 256 B, triple-buffered SMEM)
//   2. GATE: tid 0 acquire-polls ALL 8 counter words until each >= 128*t
//      (8 independent loads/iter -> MLP'd; still ONE global poller per CTA)
//   3. bar A (gate fanout; acquire edge extends CTA-wide through the bar)
//   4. SWEEP: one WEAK __ldcg float4 per thread -> hs[t&1]
//   5. bar B (orders sweep reads/STS before matvec reads AND before the
//      release-reds below — double duty)
//   6. matvec (LDS.64 + FMA2, W_hh + W_ih) -> shfl reduce -> activations
//   7. lane 0: __stcg h_{t+1}[u]; red.release.gpu.add(g_cnt8[wrp], 1)
//      — per-warp signal, fires immediately; NO trailing barrier.
//
// Gate exactness: word w hits 128*t only when warp w of EVERY CTA finished
// step t-1; all 8 words >= 128*t  <=>  all 1024 units of h_t published.
// WAR safety: writer warp stores slot (t+1)&1 only in step t+1, after its
// CTA's gate saw all step-t reds; each red (release) is ordered after bar B
// of its step, which is after ALL that CTA's threads' sweep reads of slot
// (t-1)&1 — precisely the slot step-(t+1) writers clobber. Covered.
// hs/xs intra-CTA WAR: bars A+B each step bound warp skew to < 1 step;
// hs double-buffer and xs triple-buffer cover it.
// ---------------------------------------------------------------------------
__global__ void __launch_bounds__(256, 1) rec_kernel(
    const float* __restrict__ x,
    const float* __restrict__ Wih,
    const float* __restrict__ Whh,
    const float* __restrict__ bih,
    const float* __restrict__ bhh)
{
    __shared__ __align__(16) float hs[2][H];     // staged h_t
    __shared__ __align__(16) float xs[3][II];    // staged x_t (triple buffer)

    const int tid  = threadIdx.x;
    const int lane = tid & 31;
    const int wrp  = tid >> 5;               // 0..7
    const int u    = blockIdx.x * UPC + wrp; // hidden unit 0..1023

    // ---- W_hh slice into registers (coalesced float2 loads) ----
    unsigned long long wq[4][16];
    #pragma unroll
    for (int g = 0; g < 4; g++) {
        const float2* base = (const float2*)(Whh + (size_t)(g * H + u) * H) + lane;
        #pragma unroll
        for (int k = 0; k < 16; k++) {
            float2 v = base[k * 32];
            wq[g][k] = pk2(v.x, v.y);
        }
    }
    // ---- W_ih slice (cols 2l, 2l+1 of rows u, H+u, 2H+u, 3H+u) ----
    unsigned long long wx[4];
    #pragma unroll
    for (int g = 0; g < 4; g++) {
        float2 v = ((const float2*)(Wih + (size_t)(g * H + u) * II))[lane];
        wx[g] = pk2(v.x, v.y);
    }
    // ---- biases (only lane 0 consumes them) ----
    float bs0 = bih[u]         + bhh[u];
    float bs1 = bih[H + u]     + bhh[H + u];
    float bs2 = bih[2 * H + u] + bhh[2 * H + u];
    float bs3 = bih[3 * H + u] + bhh[3 * H + u];

    // ---- preload x_0 into xs[0] ----
    if (tid < 16) ((float4*)xs[0])[tid] = ((const float4*)x)[tid];
    __syncthreads();

    float c = 0.0f;                          // cell state (lane 0 only)
    const unsigned full = 0xffffffffu;

    #pragma unroll 1
    for (int t = 0; t < S; t++) {
        const int cur = t & 1;

        // 1. prefetch next step's input row (DRAM, hidden behind this step)
        if (t + 1 < S && tid < 16)
            ((float4*)xs[(t + 1) % 3])[tid] =
                __ldcg((const float4*)(x + (size_t)(t + 1) * II) + tid);

        // 2. GATE: tid 0 acquire-polls all 8 sharded counters (MLP'd)
        if (t > 0 && tid == 0) {
            const unsigned need = (unsigned)t * NCTA;
            for (;;) {
                unsigned v0, v1, v2, v3, v4, v5, v6, v7;
                asm volatile("ld.acquire.gpu.global.u32 %0, [%1];" : "=r"(v0) : "l"(g_cnt8 + 0*CSTRIDE));
                asm volatile("ld.acquire.gpu.global.u32 %0, [%1];" : "=r"(v1) : "l"(g_cnt8 + 1*CSTRIDE));
                asm volatile("ld.acquire.gpu.global.u32 %0, [%1];" : "=r"(v2) : "l"(g_cnt8 + 2*CSTRIDE));
                asm volatile("ld.acquire.gpu.global.u32 %0, [%1];" : "=r"(v3) : "l"(g_cnt8 + 3*CSTRIDE));
                asm volatile("ld.acquire.gpu.global.u32 %0, [%1];" : "=r"(v4) : "l"(g_cnt8 + 4*CSTRIDE));
                asm volatile("ld.acquire.gpu.global.u32 %0, [%1];" : "=r"(v5) : "l"(g_cnt8 + 5*CSTRIDE));
                asm volatile("ld.acquire.gpu.global.u32 %0, [%1];" : "=r"(v6) : "l"(g_cnt8 + 6*CSTRIDE));
                asm volatile("ld.acquire.gpu.global.u32 %0, [%1];" : "=r"(v7) : "l"(g_cnt8 + 7*CSTRIDE));
                unsigned mn = min(min(min(v0, v1), min(v2, v3)),
                                  min(min(v4, v5), min(v6, v7)));
                if (mn >= need) break;
            }
        }
        __syncthreads();                     // bar A (gate fanout)

        // 3. SWEEP: single weak 16B load per thread (data stable post-gate)
        ((float4*)hs[cur])[tid] = __ldcg(((const float4*)g_h[cur]) + tid);
        __syncthreads();                     // bar B

        // 4. mat-vec: W_hh * h_t  +  W_ih * x_t  (all packed f32x2)
        unsigned long long a0 = 0ull, a1 = 0ull, a2 = 0ull, a3 = 0ull;
        const unsigned long long* h2p = (const unsigned long long*)hs[cur] + lane;
        #pragma unroll
        for (int k = 0; k < 16; k++) {
            unsigned long long hv = h2p[k * 32];
            FMA2(a0, wq[0][k], hv);
            FMA2(a1, wq[1][k], hv);
            FMA2(a2, wq[2][k], hv);
            FMA2(a3, wq[3][k], hv);
        }
        {
            unsigned long long xv = ((const unsigned long long*)xs[t % 3])[lane];
            FMA2(a0, wx[0], xv);
            FMA2(a1, wx[1], xv);
            FMA2(a2, wx[2], xv);
            FMA2(a3, wx[3], xv);
        }
        float s0, s1, s2, s3, xl, xh;
        upk2(a0, xl, xh); s0 = xl + xh;
        upk2(a1, xl, xh); s1 = xl + xh;
        upk2(a2, xl, xh); s2 = xl + xh;
        upk2(a3, xl, xh); s3 = xl + xh;

        #pragma unroll
        for (int off = 16; off > 0; off >>= 1) {
            s0 += __shfl_xor_sync(full, s0, off);
            s1 += __shfl_xor_sync(full, s1, off);
            s2 += __shfl_xor_sync(full, s2, off);
            s3 += __shfl_xor_sync(full, s3, off);
        }

        // 5. activations + publish + immediate per-warp release signal
        if (lane == 0) {
            const float i_ = sigf(s0 + bs0);
            const float f_ = sigf(s1 + bs1);
            const float g_ = tanhfast(s2 + bs2);
            const float o_ = sigf(s3 + bs3);
            c = fmaf(f_, c, i_ * g_);
            const float hnew = o_ * tanhfast(c);
            __stcg(&g_h[(t + 1) & 1][u], hnew);
            asm volatile("red.release.gpu.global.add.u32 [%0], %1;"
                         :: "l"(g_cnt8 + wrp * CSTRIDE), "r"(1u));
        }
        // no trailing bar: bar A of the next iteration re-aligns warps
    }
}

// ---------------------------------------------------------------------------
// Kernel 2: out = h_S @ W_lin^T + b_lin   (O = 1)
// h_S lives in g_h[S & 1] = g_h[0]
// ---------------------------------------------------------------------------
__global__ void __launch_bounds__(1024) out_kernel(
    const float* __restrict__ Wlin,
    const float* __restrict__ blin,
    float* __restrict__ out)
{
    __shared__ float red[32];
    const int tid = threadIdx.x;
    float v = g_h[0][tid] * Wlin[tid];
    #pragma unroll
    for (int off = 16; off > 0; off >>= 1)
        v += __shfl_xor_sync(0xffffffffu, v, off);
    if ((tid & 31) == 0) red[tid >> 5] = v;
    __syncthreads();
    if (tid < 32) {
        float xv = red[tid];
        #pragma unroll
        for (int off = 16; off > 0; off >>= 1)
            xv += __shfl_xor_sync(0xffffffffu, xv, off);
        if (tid == 0) out[0] = xv + blin[0];
    }
}

// ---------------------------------------------------------------------------
// kernel_launch (graph-capturable: plain launches only)
// Input order: input_seq, W_ih, W_hh, b_ih, b_hh, W_lin, b_lin (all fp32)
// ---------------------------------------------------------------------------
extern "C" void kernel_launch(void* const* d_in, const int* in_sizes, int n_in,
                              void* d_out, int out_size)
{
    const float* x    = (const float*)d_in[0];
    const float* Wih  = (const float*)d_in[1];
    const float* Whh  = (const float*)d_in[2];
    const float* bih  = (const float*)d_in[3];
    const float* bhh  = (const float*)d_in[4];
    const float* Wlin = (const float*)d_in[5];
    const float* blin = (const float*)d_in[6];
    float* out = (float*)d_out;

    reset_kernel<<<1, 1024>>>();
    rec_kernel<<<NCTA, 256>>>(x, Wih, Whh, bih, bhh);
    out_kernel<<<1, 1024>>>(Wlin, blin, out);
}

// round 14
// speedup vs baseline: 2.5059x; 2.5059x over previous
#include <cuda_runtime.h>
#include <cstdint>

// Problem sizes
#define S    4096
#define II   64
#define H    1024
#define NCTA 128
#define UPC  8        // hidden units per CTA (1 per compute warp, 8 warps)
#define NTH  288      // 256 compute threads + 32-thread dedicated sync warp

// ---------------------------------------------------------------------------
// Device-global scratch (allocation-free rule: __device__ arrays only)
//
// g_h:  double-buffered hidden state (plain f32; h_t lives in slot t&1).
// g_cnt: monotonic CTA-step counter — the ONLY globally polled/updated word.
//   Law (R3/R7/R9/R11/R12/R13): exactly 128 pollers + 128 REDs per step on
//   ONE line is the proven optimum; every deviation regressed 25-170%.
//
// Visibility chain (all pieces empirically proven):
//   producer warps publish h (weak __stcg) -> named bar(256) -> tid0
//   red.release.gpu (cumulative over the CTA's stores) -> sync warp
//   ld.acquire.gpu sees count -> st.release.cta(SMEM flag) -> compute warps
//   ld.acquire.cta flag -> weak __ldcg sweep reads fresh h.
// ---------------------------------------------------------------------------
__device__ float    g_h[2][H];
__device__ unsigned g_cnt;

// ---------------------------------------------------------------------------
// Helpers
// ---------------------------------------------------------------------------
__device__ __forceinline__ unsigned long long pk2(float x, float y) {
    unsigned long long r;
    asm("mov.b64 %0, {%1,%2};" : "=l"(r) : "f"(x), "f"(y));
    return r;
}
__device__ __forceinline__ void upk2(unsigned long long a, float& x, float& y) {
    asm("mov.b64 {%0,%1}, %2;" : "=f"(x), "=f"(y) : "l"(a));
}
#define FMA2(acc, a, b) \
    asm("fma.rn.f32x2 %0, %1, %2, %0;" : "+l"(acc) : "l"(a), "l"(b))
#define CBAR() asm volatile("bar.sync 1, 256;" ::: "memory")   // compute warps only

__device__ __forceinline__ float sigf(float x) {
    return 1.0f / (1.0f + __expf(-x));
}
__device__ __forceinline__ float tanhfast(float x) {
    float ax = fabsf(x);
    float e  = __expf(-2.0f * ax);          // in (0,1], overflow-free
    float t  = __fdividef(1.0f - e, 1.0f + e);
    return copysignf(t, x);
}

// ---------------------------------------------------------------------------
// Kernel 0: reset state between graph replays (determinism requirement)
// ---------------------------------------------------------------------------
__global__ void reset_kernel() {
    int i = threadIdx.x;
    if (i < H) { g_h[0][i] = 0.0f; g_h[1][i] = 0.0f; }
    if (i == 0) g_cnt = 0u;
}

// ---------------------------------------------------------------------------
// Kernel 1: persistent fused LSTM recurrence (input GEMM folded in).
// 128 CTAs x 288 threads, 1 CTA/SM. Compute warp w (0..7) owns hidden unit
// u = cta*8 + w (gate rows u, H+u, 2H+u, 3H+u); lane l holds W_hh column
// pairs (2l+64k) k=0..15 (64 packed f32x2) + W_ih column pair 2l in regs.
// Warp 8 = SYNC WARP: lane 0 tight-polls g_cnt and fans out via SMEM flag.
// Polling OVERLAPS the compute warps' publish/trailing-bar phase, and gate
// fanout is a ~30cy LDS spin instead of a full-CTA barrier wakeup.
//
// Per-step compute-warp protocol (TWO named bars):
//   1. prefetch x_{t+1} (tid<16, 256 B, triple-buffered SMEM)
//   2. spin ld.acquire.cta on SMEM flag until >= t  (broadcast LDS, ~30cy)
//   3. SWEEP: one WEAK __ldcg float4 per thread -> hs[t&1]
//   4. CBAR (bar B: stage-writes vs matvec reads)
//   5. matvec (LDS.64 + FMA2, W_hh + W_ih) -> shfl reduce -> activations
//   6. lane 0: weak __stcg publish of h_{t+1}[u]
//   7. CBAR (trailing); tid 0: red.release.gpu.add(g_cnt, 1)
//
// Gate exactness: cnt >= 128*t iff every CTA finished step t-1 (each CTA's
// red postdates all 8 of its publishes via the trailing named bar).
// WAR safety: slot (t+1)&1 rewritten only in step t+1, gated on
// cnt >= 128(t+1); each CTA's step-t red is ordered (bar + release) after
// all that CTA's sweep reads of slot (t-1)&1 — the slot being clobbered.
// Intra-CTA: two named bars/step bound compute-warp skew to < 1 step;
// hs double-buffer + xs triple-buffer cover it. Sync warp free-runs; it
// only writes the monotonic flag, never touches hs/xs.
// ---------------------------------------------------------------------------
__global__ void __launch_bounds__(NTH, 1) rec_kernel(
    const float* __restrict__ x,
    const float* __restrict__ Wih,
    const float* __restrict__ Whh,
    const float* __restrict__ bih,
    const float* __restrict__ bhh)
{
    __shared__ __align__(16) float hs[2][H];     // staged h_t
    __shared__ __align__(16) float xs[3][II];    // staged x_t (triple buffer)
    __shared__ unsigned gflag;                   // monotonic step flag

    const int tid  = threadIdx.x;
    const int lane = tid & 31;
    const int wrp  = tid >> 5;               // 0..8

    const unsigned fa = (unsigned)__cvta_generic_to_shared(&gflag);

    if (tid == 0) gflag = 0u;
    __syncthreads();                          // ONE full-CTA barrier (all 9 warps)

    // ======================= SYNC WARP (warp 8) ==========================
    if (wrp == 8) {
        if (lane == 0) {
            #pragma unroll 1
            for (unsigned t = 1; t < S; t++) {
                const unsigned need = t * NCTA;
                unsigned v;
                do {
                    asm volatile("ld.acquire.gpu.global.u32 %0, [%1];"
                                 : "=r"(v) : "l"(&g_cnt));
                } while (v < need);
                asm volatile("st.release.cta.shared.u32 [%0], %1;"
                             :: "r"(fa), "r"(t));
            }
        }
        return;                               // whole sync warp exits the protocol
    }

    // ======================= COMPUTE WARPS (0..7) ========================
    const int u = blockIdx.x * UPC + wrp;     // hidden unit 0..1023

    // ---- W_hh slice into registers (coalesced float2 loads) ----
    unsigned long long wq[4][16];
    #pragma unroll
    for (int g = 0; g < 4; g++) {
        const float2* base = (const float2*)(Whh + (size_t)(g * H + u) * H) + lane;
        #pragma unroll
        for (int k = 0; k < 16; k++) {
            float2 v = base[k * 32];
            wq[g][k] = pk2(v.x, v.y);
        }
    }
    // ---- W_ih slice (cols 2l, 2l+1 of rows u, H+u, 2H+u, 3H+u) ----
    unsigned long long wx[4];
    #pragma unroll
    for (int g = 0; g < 4; g++) {
        float2 v = ((const float2*)(Wih + (size_t)(g * H + u) * II))[lane];
        wx[g] = pk2(v.x, v.y);
    }
    // ---- biases (only lane 0 consumes them) ----
    float bs0 = bih[u]         + bhh[u];
    float bs1 = bih[H + u]     + bhh[H + u];
    float bs2 = bih[2 * H + u] + bhh[2 * H + u];
    float bs3 = bih[3 * H + u] + bhh[3 * H + u];

    // ---- preload x_0 into xs[0] ----
    if (tid < 16) ((float4*)xs[0])[tid] = ((const float4*)x)[tid];
    CBAR();

    float c = 0.0f;                          // cell state (lane 0 only)
    const unsigned full = 0xffffffffu;

    #pragma unroll 1
    for (int t = 0; t < S; t++) {
        const int cur = t & 1;

        // 1. prefetch next step's input row (DRAM, hidden behind this step)
        if (t + 1 < S && tid < 16)
            ((float4*)xs[(t + 1) % 3])[tid] =
                __ldcg((const float4*)(x + (size_t)(t + 1) * II) + tid);

        // 2. gate fanout: cheap SMEM spin on the sync warp's flag
        if (t > 0) {
            unsigned f;
            do {
                asm volatile("ld.acquire.cta.shared.u32 %0, [%1];"
                             : "=r"(f) : "r"(fa));
            } while (f < (unsigned)t);
        }

        // 3. SWEEP: single weak 16B load per thread (data stable post-gate)
        ((float4*)hs[cur])[tid] = __ldcg(((const float4*)g_h[cur]) + tid);
        CBAR();                              // bar B

        // 4. mat-vec: W_hh * h_t  +  W_ih * x_t  (all packed f32x2)
        unsigned long long a0 = 0ull, a1 = 0ull, a2 = 0ull, a3 = 0ull;
        const unsigned long long* h2p = (const unsigned long long*)hs[cur] + lane;
        #pragma unroll
        for (int k = 0; k < 16; k++) {
            unsigned long long hv = h2p[k * 32];
            FMA2(a0, wq[0][k], hv);
            FMA2(a1, wq[1][k], hv);
            FMA2(a2, wq[2][k], hv);
            FMA2(a3, wq[3][k], hv);
        }
        {
            unsigned long long xv = ((const unsigned long long*)xs[t % 3])[lane];
            FMA2(a0, wx[0], xv);
            FMA2(a1, wx[1], xv);
            FMA2(a2, wx[2], xv);
            FMA2(a3, wx[3], xv);
        }
        float s0, s1, s2, s3, xl, xh;
        upk2(a0, xl, xh); s0 = xl + xh;
        upk2(a1, xl, xh); s1 = xl + xh;
        upk2(a2, xl, xh); s2 = xl + xh;
        upk2(a3, xl, xh); s3 = xl + xh;

        #pragma unroll
        for (int off = 16; off > 0; off >>= 1) {
            s0 += __shfl_xor_sync(full, s0, off);
            s1 += __shfl_xor_sync(full, s1, off);
            s2 += __shfl_xor_sync(full, s2, off);
            s3 += __shfl_xor_sync(full, s3, off);
        }

        // 5. activations + publish (lane 0)
        if (lane == 0) {
            const float i_ = sigf(s0 + bs0);
            const float f_ = sigf(s1 + bs1);
            const float g_ = tanhfast(s2 + bs2);
            const float o_ = sigf(s3 + bs3);
            c = fmaf(f_, c, i_ * g_);
            const float hnew = o_ * tanhfast(c);
            __stcg(&g_h[(t + 1) & 1][u], hnew);
        }

        // 6. trailing named bar + single CTA-completion signal
        CBAR();
        if (tid == 0)
            asm volatile("red.release.gpu.global.add.u32 [%0], %1;"
                         :: "l"(&g_cnt), "r"(1u));
    }
}

// ---------------------------------------------------------------------------
// Kernel 2: out = h_S @ W_lin^T + b_lin   (O = 1)
// h_S lives in g_h[S & 1] = g_h[0]
// ---------------------------------------------------------------------------
__global__ void __launch_bounds__(1024) out_kernel(
    const float* __restrict__ Wlin,
    const float* __restrict__ blin,
    float* __restrict__ out)
{
    __shared__ float red[32];
    const int tid = threadIdx.x;
    float v = g_h[0][tid] * Wlin[tid];
    #pragma unroll
    for (int off = 16; off > 0; off >>= 1)
        v += __shfl_xor_sync(0xffffffffu, v, off);
    if ((tid & 31) == 0) red[tid >> 5] = v;
    __syncthreads();
    if (tid < 32) {
        float xv = red[tid];
        #pragma unroll
        for (int off = 16; off > 0; off >>= 1)
            xv += __shfl_xor_sync(0xffffffffu, xv, off);
        if (tid == 0) out[0] = xv + blin[0];
    }
}

// ---------------------------------------------------------------------------
// kernel_launch (graph-capturable: plain launches only)
// Input order: input_seq, W_ih, W_hh, b_ih, b_hh, W_lin, b_lin (all fp32)
// ---------------------------------------------------------------------------
extern "C" void kernel_launch(void* const* d_in, const int* in_sizes, int n_in,
                              void* d_out, int out_size)
{
    const float* x    = (const float*)d_in[0];
    const float* Wih  = (const float*)d_in[1];
    const float* Whh  = (const float*)d_in[2];
    const float* bih  = (const float*)d_in[3];
    const float* bhh  = (const float*)d_in[4];
    const float* Wlin = (const float*)d_in[5];
    const float* blin = (const float*)d_in[6];
    float* out = (float*)d_out;

    reset_kernel<<<1, 1024>>>();
    rec_kernel<<<NCTA, NTH>>>(x, Wih, Whh, bih, bhh);
    out_kernel<<<1, 1024>>>(Wlin, blin, out);
}